// round 8
// baseline (speedup 1.0000x reference)
#include <cuda_runtime.h>
#include <cuda_fp16.h>
#include <cstdint>

#define NB 4096
#define NC 64
#define DD 32
#define KK 1024   // H1*H2

// ---------------------------------------------------------------- W fragments
// K matrix pre-converted to fp16, laid out per mma.m16n8k16 A-fragment:
// g_Wf16[ch(64)][mt(4)][lane(32)] = uint4 {a0,a1,a2,a3} (each fp16x2).
// a0=(r, k0|k0+1) a1=(r+8, ..) a2=(r, k0+8|k0+9) a3=(r+8, ..),
// r = 16*mt + lane/4, k0 = 2*(lane%4); global k = 16*ch + klocal.
// Padded by 2 chunks so the pipelined tail prefetch stays in-bounds.
__device__ __align__(16) uint4 g_Wf16[66 * 4 * 32];

__global__ void wfrag_kernel(const float* __restrict__ K) {
    int idx = blockIdx.x * blockDim.x + threadIdx.x;  // 8192
    int lane = idx & 31, mt = (idx >> 5) & 3, ch = idx >> 7;
    int r0 = 16 * mt + (lane >> 2);
    int k0 = 16 * ch + 2 * (lane & 3);
    uint32_t q[4];
#pragma unroll
    for (int u = 0; u < 4; u++) {
        int r = r0 + (u & 1) * 8;
        int k = k0 + (u >> 1) * 8;
        __half2 h = __floats2half2_rn(K[r * KK + k], K[r * KK + k + 1]);
        q[u] = *(uint32_t*)&h;
    }
    g_Wf16[idx] = make_uint4(q[0], q[1], q[2], q[3]);
}

// ---------------------------------------------------------------- helpers
__device__ __forceinline__ uint32_t f16x2_of(float hi, float lo) {
    uint32_t r;
    asm("cvt.rn.f16x2.f32 %0, %1, %2;" : "=r"(r) : "f"(hi), "f"(lo));
    return r;
}
__device__ __forceinline__ void mma_f16(float& c0, float& c1, float& c2, float& c3,
                                        uint32_t a0, uint32_t a1, uint32_t a2,
                                        uint32_t a3, uint32_t b0, uint32_t b1) {
    asm volatile(
        "mma.sync.aligned.m16n8k16.row.col.f32.f16.f16.f32 "
        "{%0,%1,%2,%3}, {%4,%5,%6,%7}, {%8,%9}, {%0,%1,%2,%3};"
        : "+f"(c0), "+f"(c1), "+f"(c2), "+f"(c3)
        : "r"(a0), "r"(a1), "r"(a2), "r"(a3), "r"(b0), "r"(b1));
}

// ---------------------------------------------------------------- main kernel
// CTA: 256 threads = 8 warps = 4 batches; 2 warps per batch (m-split):
// warp (w&1) covers m-tiles {2*(w&1), 2*(w&1)+1} for all 32 d-columns.
// Per-batch GEMM: OUT[c(64), d(32)] = W[c,k] * Z[k,d], K=1024, fp16 1-pass.
// Mainloop over i (=ch/2) with software pipelining: next-i xi + next A
// fragments are prefetched before the current 16 MMAs are issued.
__global__ __launch_bounds__(256, 2)
void cin_mma_kernel(const float* __restrict__ X, const float* __restrict__ Y,
                    float* __restrict__ out_mat, float* __restrict__ out_fin) {
    __shared__ float x_s[4 * KK + 64];   // +64 pad: tail prefetch in-bounds

    const int t = threadIdx.x;
    const int lane = t & 31;
    const int w = t >> 5;
    const int bl = w >> 1;            // local batch 0..3
    const int mh = w & 1;             // m-half: m-tiles {2*mh, 2*mh+1}
    const int b = blockIdx.x * 4 + bl;
    const int g = lane >> 2;          // row group / d offset
    const int jm = lane & 3;

    // stage x (coalesced float4)
    {
        const float4* xg = (const float4*)(X + (size_t)blockIdx.x * 4 * KK);
        float4* xs4 = (float4*)x_s;
#pragma unroll
        for (int rep = 0; rep < 4; rep++) xs4[rep * 256 + t] = xg[rep * 256 + t];
        if (t < 16) xs4[1024 + t] = make_float4(0.f, 0.f, 0.f, 0.f);
    }
    __syncthreads();

    // y values this thread's B-fragment slots need.
    // B frag (n8k16 col): b0 <- klocal {2jm,2jm+1}, b1 <- {2jm+8,2jm+9};
    // j = p*16 + klocal; y8[nf][4p+u] as in layout comment. d = g + 8*nf.
    const float* yb = Y + (size_t)b * KK;
    float y8[4][8];
#pragma unroll
    for (int nf = 0; nf < 4; nf++) {
        int d = g + 8 * nf;
#pragma unroll
        for (int p = 0; p < 2; p++) {
            y8[nf][4 * p + 0] = yb[(16 * p + 2 * jm) * 32 + d];
            y8[nf][4 * p + 1] = yb[(16 * p + 2 * jm + 1) * 32 + d];
            y8[nf][4 * p + 2] = yb[(16 * p + 8 + 2 * jm) * 32 + d];
            y8[nf][4 * p + 3] = yb[(16 * p + 8 + 2 * jm + 1) * 32 + d];
        }
    }

    float acc[2][4][4];
#pragma unroll
    for (int m = 0; m < 2; m++)
#pragma unroll
        for (int n = 0; n < 4; n++)
#pragma unroll
            for (int q = 0; q < 4; q++) acc[m][n][q] = 0.0f;

    // A pointer for this warp's m-tiles: index = ch*128 + m*32 (+ base)
    const uint4* Wp = g_Wf16 + (2 * mh) * 32 + lane;
    const float* xrowg = x_s + bl * KK + g;

    // ---- pipeline state
    uint4 a[2][2];                 // [parity p][m]
    float xi[4];                   // current i's x values per nf
    uint32_t bf[2][4][2];          // [p][nf][reg]

    // prologue: i = 0
#pragma unroll
    for (int nf = 0; nf < 4; nf++) xi[nf] = xrowg[8 * nf];
    a[0][0] = Wp[0];   a[0][1] = Wp[32];          // ch 0
    a[1][0] = Wp[128]; a[1][1] = Wp[160];         // ch 1
#pragma unroll
    for (int p = 0; p < 2; p++)
#pragma unroll
        for (int nf = 0; nf < 4; nf++) {
            bf[p][nf][0] = f16x2_of(xi[nf] * y8[nf][4 * p + 1],
                                    xi[nf] * y8[nf][4 * p + 0]);
            bf[p][nf][1] = f16x2_of(xi[nf] * y8[nf][4 * p + 3],
                                    xi[nf] * y8[nf][4 * p + 2]);
        }

#pragma unroll 2
    for (int i = 0; i < 32; i++) {
        // prefetch next i's xi (pad makes i=31 access safe & dead)
        float xin[4];
#pragma unroll
        for (int nf = 0; nf < 4; nf++) xin[nf] = xrowg[(i + 1) * 32 + 8 * nf];

        // MMAs for chunk 2i (p=0), then prefetch A for chunk 2i+2
#pragma unroll
        for (int m = 0; m < 2; m++)
#pragma unroll
            for (int nf = 0; nf < 4; nf++)
                mma_f16(acc[m][nf][0], acc[m][nf][1], acc[m][nf][2],
                        acc[m][nf][3], a[0][m].x, a[0][m].y, a[0][m].z,
                        a[0][m].w, bf[0][nf][0], bf[0][nf][1]);
        a[0][0] = Wp[(2 * i + 2) * 128];
        a[0][1] = Wp[(2 * i + 2) * 128 + 32];

        // MMAs for chunk 2i+1 (p=1), then prefetch A for chunk 2i+3
#pragma unroll
        for (int m = 0; m < 2; m++)
#pragma unroll
            for (int nf = 0; nf < 4; nf++)
                mma_f16(acc[m][nf][0], acc[m][nf][1], acc[m][nf][2],
                        acc[m][nf][3], a[1][m].x, a[1][m].y, a[1][m].z,
                        a[1][m].w, bf[1][nf][0], bf[1][nf][1]);
        a[1][0] = Wp[(2 * i + 3) * 128];
        a[1][1] = Wp[(2 * i + 3) * 128 + 32];

        // build next i's B fragments
#pragma unroll
        for (int p = 0; p < 2; p++)
#pragma unroll
            for (int nf = 0; nf < 4; nf++) {
                bf[p][nf][0] = f16x2_of(xin[nf] * y8[nf][4 * p + 1],
                                        xin[nf] * y8[nf][4 * p + 0]);
                bf[p][nf][1] = f16x2_of(xin[nf] * y8[nf][4 * p + 3],
                                        xin[nf] * y8[nf][4 * p + 2]);
            }
    }

    // ----- epilogue: D frag rows c = 16*(2*mh+m) + g (+8),
    // cols d = 8*nf + 2*jm + {0,1}. Each warp owns distinct c rows.
    float* om = out_mat + (size_t)b * (NC * DD);
    float* fb = out_fin + (size_t)b * NC;
#pragma unroll
    for (int m = 0; m < 2; m++) {
        const int c0 = 16 * (2 * mh + m) + g;
        float s0 = 0.0f, s1 = 0.0f;
#pragma unroll
        for (int nf = 0; nf < 4; nf++) {
            int d0 = 8 * nf + 2 * jm;
            *(float2*)&om[c0 * DD + d0] =
                make_float2(acc[m][nf][0], acc[m][nf][1]);
            *(float2*)&om[(c0 + 8) * DD + d0] =
                make_float2(acc[m][nf][2], acc[m][nf][3]);
            s0 += acc[m][nf][0] + acc[m][nf][1];
            s1 += acc[m][nf][2] + acc[m][nf][3];
        }
#pragma unroll
        for (int o = 1; o <= 2; o <<= 1) {
            s0 += __shfl_xor_sync(0xffffffffu, s0, o);
            s1 += __shfl_xor_sync(0xffffffffu, s1, o);
        }
        if (jm == 0) { fb[c0] = s0; fb[c0 + 8] = s1; }
    }
}

extern "C" void kernel_launch(void* const* d_in, const int* in_sizes, int n_in,
                              void* d_out, int out_size) {
    const float* X = (const float*)d_in[0];
    const float* Y = (const float*)d_in[1];
    const float* K = (const float*)d_in[2];
    float* om = (float*)d_out;
    float* fin = om + (size_t)NB * NC * DD;

    wfrag_kernel<<<32, 256>>>(K);
    cin_mma_kernel<<<NB / 4, 256>>>(X, Y, om, fin);
}

// round 9
// speedup vs baseline: 1.5409x; 1.5409x over previous
#include <cuda_runtime.h>
#include <cuda_fp16.h>
#include <cstdint>

#define NB 4096
#define NC 64
#define DD 32
#define KK 1024   // H1*H2

// ---------------------------------------------------------------- W fragments
// K matrix pre-converted to fp16, laid out per mma.m16n8k16 A-fragment:
// g_Wf16[ch(64)][mt(4)][lane(32)] = uint4 {a0,a1,a2,a3} (each fp16x2).
// a0=(r, k0|k0+1) a1=(r+8, ..) a2=(r, k0+8|k0+9) a3=(r+8, ..),
// r = 16*mt + lane/4, k0 = 2*(lane%4); global k = 16*ch + klocal.
__device__ __align__(16) uint4 g_Wf16[64 * 4 * 32];

__global__ void wfrag_kernel(const float* __restrict__ K) {
    int idx = blockIdx.x * blockDim.x + threadIdx.x;  // 8192
    int lane = idx & 31, mt = (idx >> 5) & 3, ch = idx >> 7;
    int r0 = 16 * mt + (lane >> 2);
    int k0 = 16 * ch + 2 * (lane & 3);
    uint32_t q[4];
#pragma unroll
    for (int u = 0; u < 4; u++) {
        int r = r0 + (u & 1) * 8;
        int k = k0 + (u >> 1) * 8;
        __half2 h = __floats2half2_rn(K[r * KK + k], K[r * KK + k + 1]);
        q[u] = *(uint32_t*)&h;
    }
    g_Wf16[idx] = make_uint4(q[0], q[1], q[2], q[3]);
}

// ---------------------------------------------------------------- helpers
__device__ __forceinline__ uint32_t f16x2_of(float hi, float lo) {
    uint32_t r;
    asm("cvt.rn.f16x2.f32 %0, %1, %2;" : "=r"(r) : "f"(hi), "f"(lo));
    return r;
}
__device__ __forceinline__ uint32_t hmul2(uint32_t a, uint32_t b) {
    uint32_t r;
    asm("mul.f16x2 %0, %1, %2;" : "=r"(r) : "r"(a), "r"(b));
    return r;
}
__device__ __forceinline__ void mma_f16(float& c0, float& c1, float& c2, float& c3,
                                        uint32_t a0, uint32_t a1, uint32_t a2,
                                        uint32_t a3, uint32_t b0, uint32_t b1) {
    asm volatile(
        "mma.sync.aligned.m16n8k16.row.col.f32.f16.f16.f32 "
        "{%0,%1,%2,%3}, {%4,%5,%6,%7}, {%8,%9}, {%0,%1,%2,%3};"
        : "+f"(c0), "+f"(c1), "+f"(c2), "+f"(c3)
        : "r"(a0), "r"(a1), "r"(a2), "r"(a3), "r"(b0), "r"(b1));
}

// ---------------------------------------------------------------- main kernel
// CTA: 256 threads = 8 warps = 4 batches; 2 warps per batch (m-split):
// warp (w&1) covers m-tiles {2*(w&1), 2*(w&1)+1} for all 32 d-columns.
// Per-batch GEMM: OUT[c(64), d(32)] = W[c,k] * Z[k,d], K=1024, fp16 1-pass.
// y held pre-packed as f16x2 (16 regs); B-fragments via HMUL2 against a
// splatted fp16 xi. Target 3 CTAs/SM (<=85 regs) for latency hiding.
__global__ __launch_bounds__(256, 3)
void cin_mma_kernel(const float* __restrict__ X, const float* __restrict__ Y,
                    float* __restrict__ out_mat, float* __restrict__ out_fin) {
    __shared__ float x_s[4 * KK];   // 16 KB: x for the CTA's 4 batches

    const int t = threadIdx.x;
    const int lane = t & 31;
    const int w = t >> 5;
    const int bl = w >> 1;            // local batch 0..3
    const int mh = w & 1;             // m-half: m-tiles {2*mh, 2*mh+1}
    const int b = blockIdx.x * 4 + bl;
    const int g = lane >> 2;          // row group / d offset
    const int jm = lane & 3;

    // stage x (coalesced float4)
    {
        const float4* xg = (const float4*)(X + (size_t)blockIdx.x * 4 * KK);
        float4* xs4 = (float4*)x_s;
#pragma unroll
        for (int rep = 0; rep < 4; rep++) xs4[rep * 256 + t] = xg[rep * 256 + t];
    }
    __syncthreads();

    // y pre-packed f16x2. B frag (n8k16 col): b0 <- klocal {2jm, 2jm+1},
    // b1 <- {2jm+8, 2jm+9}; j = p*16 + klocal; d = g + 8*nf.
    // y2[nf][2p+r]: r=0 -> j = 16p+2jm (lo), +1 (hi); r=1 -> j = 16p+8+2jm.
    const float* yb = Y + (size_t)b * KK;
    uint32_t y2[4][4];
#pragma unroll
    for (int nf = 0; nf < 4; nf++) {
        int d = g + 8 * nf;
#pragma unroll
        for (int p = 0; p < 2; p++) {
            y2[nf][2 * p] = f16x2_of(yb[(16 * p + 2 * jm + 1) * 32 + d],
                                     yb[(16 * p + 2 * jm) * 32 + d]);
            y2[nf][2 * p + 1] = f16x2_of(yb[(16 * p + 8 + 2 * jm + 1) * 32 + d],
                                         yb[(16 * p + 8 + 2 * jm) * 32 + d]);
        }
    }

    float acc[2][4][4];
#pragma unroll
    for (int m = 0; m < 2; m++)
#pragma unroll
        for (int n = 0; n < 4; n++)
#pragma unroll
            for (int q = 0; q < 4; q++) acc[m][n][q] = 0.0f;

    const uint4* W4 = g_Wf16;          // [ch*128 + mt*32 + lane]
    const float* xrow = x_s + bl * KK;

#pragma unroll 2
    for (int ch = 0; ch < 64; ch++) {
        const int i = ch >> 1;
        const int p = ch & 1;

        // B fragments: bf[nf][r] = f16(xi) * y2[nf][2p+r]   (HMUL2)
        uint32_t bf[4][2];
#pragma unroll
        for (int nf = 0; nf < 4; nf++) {
            const float xi = xrow[i * 32 + g + 8 * nf];
            const uint32_t xi2 = f16x2_of(xi, xi);
            bf[nf][0] = hmul2(xi2, y2[nf][2 * p]);
            bf[nf][1] = hmul2(xi2, y2[nf][2 * p + 1]);
        }

        const int base = ch * 128 + lane;
#pragma unroll
        for (int m = 0; m < 2; m++) {
            const int mt = 2 * mh + m;
            uint4 a = W4[base + mt * 32];
#pragma unroll
            for (int nf = 0; nf < 4; nf++)
                mma_f16(acc[m][nf][0], acc[m][nf][1], acc[m][nf][2],
                        acc[m][nf][3], a.x, a.y, a.z, a.w,
                        bf[nf][0], bf[nf][1]);
        }
    }

    // ----- epilogue: D frag rows c = 16*(2*mh+m) + g (+8),
    // cols d = 8*nf + 2*jm + {0,1}. Each warp owns distinct c rows.
    float* om = out_mat + (size_t)b * (NC * DD);
    float* fb = out_fin + (size_t)b * NC;
#pragma unroll
    for (int m = 0; m < 2; m++) {
        const int c0 = 16 * (2 * mh + m) + g;
        float s0 = 0.0f, s1 = 0.0f;
#pragma unroll
        for (int nf = 0; nf < 4; nf++) {
            int d0 = 8 * nf + 2 * jm;
            *(float2*)&om[c0 * DD + d0] =
                make_float2(acc[m][nf][0], acc[m][nf][1]);
            *(float2*)&om[(c0 + 8) * DD + d0] =
                make_float2(acc[m][nf][2], acc[m][nf][3]);
            s0 += acc[m][nf][0] + acc[m][nf][1];
            s1 += acc[m][nf][2] + acc[m][nf][3];
        }
        // sum across the quad (lanes sharing g): covers all 32 d
#pragma unroll
        for (int o = 1; o <= 2; o <<= 1) {
            s0 += __shfl_xor_sync(0xffffffffu, s0, o);
            s1 += __shfl_xor_sync(0xffffffffu, s1, o);
        }
        if (jm == 0) { fb[c0] = s0; fb[c0 + 8] = s1; }
    }
}

extern "C" void kernel_launch(void* const* d_in, const int* in_sizes, int n_in,
                              void* d_out, int out_size) {
    const float* X = (const float*)d_in[0];
    const float* Y = (const float*)d_in[1];
    const float* K = (const float*)d_in[2];
    float* om = (float*)d_out;
    float* fin = om + (size_t)NB * NC * DD;

    wfrag_kernel<<<32, 256>>>(K);
    cin_mma_kernel<<<NB / 4, 256>>>(X, Y, om, fin);
}

// round 10
// speedup vs baseline: 1.6236x; 1.0537x over previous
#include <cuda_runtime.h>
#include <cuda_fp16.h>
#include <cstdint>

#define NB 4096
#define NC 64
#define DD 32
#define KK 1024   // H1*H2
#define NSTAGE 2

// ---------------------------------------------------------------- W fragments
// K matrix pre-converted to fp16, laid out per mma.m16n8k16 A-fragment:
// g_Wf16[ch(64)][mt(4)][lane(32)] = uint4 {a0,a1,a2,a3} (each fp16x2).
// a0=(r, k0|k0+1) a1=(r+8, ..) a2=(r, k0+8|k0+9) a3=(r+8, ..),
// r = 16*mt + lane/4, k0 = 2*(lane%4); global k = 16*ch + klocal.
__device__ __align__(16) uint4 g_Wf16[64 * 4 * 32];

__global__ void wfrag_kernel(const float* __restrict__ K) {
    int idx = blockIdx.x * blockDim.x + threadIdx.x;  // 8192
    int lane = idx & 31, mt = (idx >> 5) & 3, ch = idx >> 7;
    int r0 = 16 * mt + (lane >> 2);
    int k0 = 16 * ch + 2 * (lane & 3);
    uint32_t q[4];
#pragma unroll
    for (int u = 0; u < 4; u++) {
        int r = r0 + (u & 1) * 8;
        int k = k0 + (u >> 1) * 8;
        __half2 h = __floats2half2_rn(K[r * KK + k], K[r * KK + k + 1]);
        q[u] = *(uint32_t*)&h;
    }
    g_Wf16[idx] = make_uint4(q[0], q[1], q[2], q[3]);
}

// ---------------------------------------------------------------- helpers
__device__ __forceinline__ uint32_t smem_u32(const void* p) {
    uint32_t a;
    asm("{ .reg .u64 t; cvta.to.shared.u64 t, %1; cvt.u32.u64 %0, t; }"
        : "=r"(a) : "l"(p));
    return a;
}
__device__ __forceinline__ uint32_t f16x2_of(float hi, float lo) {
    uint32_t r;
    asm("cvt.rn.f16x2.f32 %0, %1, %2;" : "=r"(r) : "f"(hi), "f"(lo));
    return r;
}
__device__ __forceinline__ uint32_t hmul2(uint32_t a, uint32_t b) {
    uint32_t r;
    asm("mul.f16x2 %0, %1, %2;" : "=r"(r) : "r"(a), "r"(b));
    return r;
}
__device__ __forceinline__ void mma_f16(float& c0, float& c1, float& c2, float& c3,
                                        uint32_t a0, uint32_t a1, uint32_t a2,
                                        uint32_t a3, uint32_t b0, uint32_t b1) {
    asm volatile(
        "mma.sync.aligned.m16n8k16.row.col.f32.f16.f16.f32 "
        "{%0,%1,%2,%3}, {%4,%5,%6,%7}, {%8,%9}, {%0,%1,%2,%3};"
        : "+f"(c0), "+f"(c1), "+f"(c2), "+f"(c3)
        : "r"(a0), "r"(a1), "r"(a2), "r"(a3), "r"(b0), "r"(b1));
}
#define CP_ASYNC16(dst, src) \
    asm volatile("cp.async.cg.shared.global [%0], [%1], 16;" \
                 :: "r"(dst), "l"(src) : "memory")
#define CP_COMMIT() asm volatile("cp.async.commit_group;" ::: "memory")
#define CP_WAIT(n)  asm volatile("cp.async.wait_group %0;" :: "n"(n) : "memory")

// ---------------------------------------------------------------- main kernel
// CTA: 256 threads = 8 warps = 4 batches; 2 warps per batch (m-split):
// warp (w&1) covers m-tiles {2*(w&1), 2*(w&1)+1} for all 32 d-columns.
// Per-batch GEMM: OUT[c(64), d(32)] = W[c,k] * Z[k,d], K=1024, fp16 1-pass.
// W streamed via per-warp cp.async.cg double buffer in SMEM: each lane
// copies only its own 16B fragment, so cp.async.wait_group alone orders it
// (no CTA barriers in the mainloop; warps stay fully decoupled).
__global__ __launch_bounds__(256, 3)
void cin_mma_kernel(const float* __restrict__ X, const float* __restrict__ Y,
                    float* __restrict__ out_mat, float* __restrict__ out_fin) {
    __shared__ float x_s[4 * KK];                  // 16 KB
    __shared__ uint4 w_s[8][NSTAGE][2][32];        // 16 KB (1 KB per warp-stage)

    const int t = threadIdx.x;
    const int lane = t & 31;
    const int w = t >> 5;
    const int bl = w >> 1;            // local batch 0..3
    const int mh = w & 1;             // m-half: m-tiles {2*mh, 2*mh+1}
    const int b = blockIdx.x * 4 + bl;
    const int g = lane >> 2;          // row group / d offset
    const int jm = lane & 3;

    // stage x (coalesced float4)
    {
        const float4* xg = (const float4*)(X + (size_t)blockIdx.x * 4 * KK);
        float4* xs4 = (float4*)x_s;
#pragma unroll
        for (int rep = 0; rep < 4; rep++) xs4[rep * 256 + t] = xg[rep * 256 + t];
    }
    __syncthreads();

    // y pre-packed f16x2. B frag (n8k16 col): b0 <- klocal {2jm, 2jm+1},
    // b1 <- {2jm+8, 2jm+9}; j = p*16 + klocal; d = g + 8*nf.
    const float* yb = Y + (size_t)b * KK;
    uint32_t y2[4][4];
#pragma unroll
    for (int nf = 0; nf < 4; nf++) {
        int d = g + 8 * nf;
#pragma unroll
        for (int p = 0; p < 2; p++) {
            y2[nf][2 * p] = f16x2_of(yb[(16 * p + 2 * jm + 1) * 32 + d],
                                     yb[(16 * p + 2 * jm) * 32 + d]);
            y2[nf][2 * p + 1] = f16x2_of(yb[(16 * p + 8 + 2 * jm + 1) * 32 + d],
                                         yb[(16 * p + 8 + 2 * jm) * 32 + d]);
        }
    }

    float acc[2][4][4];
#pragma unroll
    for (int m = 0; m < 2; m++)
#pragma unroll
        for (int n = 0; n < 4; n++)
#pragma unroll
            for (int q = 0; q < 4; q++) acc[m][n][q] = 0.0f;

    // W source pointer for this warp/lane; chunk c, mtile m: gw + c*128 + m*32
    const uint4* gw = g_Wf16 + (2 * mh) * 32 + lane;
    // per-warp smem stage slots for this lane
    const uint32_t ws0 = smem_u32(&w_s[w][0][0][lane]);
    const uint32_t stage_bytes = 2 * 32 * 16;      // 1 KB per stage
    const uint32_t m_bytes = 32 * 16;

    // prologue: prefetch chunks 0 and 1
#pragma unroll
    for (int s = 0; s < NSTAGE; s++) {
        CP_ASYNC16(ws0 + s * stage_bytes, gw + s * 128);
        CP_ASYNC16(ws0 + s * stage_bytes + m_bytes, gw + s * 128 + 32);
        CP_COMMIT();
    }

    const float* xrow = x_s + bl * KK;

#pragma unroll 2
    for (int ch = 0; ch < 64; ch++) {
        const int st = ch & 1;        // stage; also p-parity (same thing here)
        const int i = ch >> 1;

        CP_WAIT(NSTAGE - 1);          // chunk ch's fragments resident

        // LDS this warp's A fragments for chunk ch (own-lane data only)
        uint4 a0 = w_s[w][st][0][lane];
        uint4 a1 = w_s[w][st][1][lane];

        // B fragments: bf[nf][r] = f16(xi) * y2[nf][2p+r]   (HMUL2)
        uint32_t bf[4][2];
#pragma unroll
        for (int nf = 0; nf < 4; nf++) {
            const float xi = xrow[i * 32 + g + 8 * nf];
            const uint32_t xi2 = f16x2_of(xi, xi);
            bf[nf][0] = hmul2(xi2, y2[nf][2 * st]);
            bf[nf][1] = hmul2(xi2, y2[nf][2 * st + 1]);
        }

#pragma unroll
        for (int nf = 0; nf < 4; nf++) {
            mma_f16(acc[0][nf][0], acc[0][nf][1], acc[0][nf][2], acc[0][nf][3],
                    a0.x, a0.y, a0.z, a0.w, bf[nf][0], bf[nf][1]);
            mma_f16(acc[1][nf][0], acc[1][nf][1], acc[1][nf][2], acc[1][nf][3],
                    a1.x, a1.y, a1.z, a1.w, bf[nf][0], bf[nf][1]);
        }

        // prefetch chunk ch+NSTAGE into the stage just freed
        if (ch + NSTAGE < 64) {
            CP_ASYNC16(ws0 + st * stage_bytes, gw + (ch + NSTAGE) * 128);
            CP_ASYNC16(ws0 + st * stage_bytes + m_bytes,
                       gw + (ch + NSTAGE) * 128 + 32);
        }
        CP_COMMIT();                  // keep 1 group per chunk (may be empty)
    }

    // ----- epilogue: D frag rows c = 16*(2*mh+m) + g (+8),
    // cols d = 8*nf + 2*jm + {0,1}. Each warp owns distinct c rows.
    float* om = out_mat + (size_t)b * (NC * DD);
    float* fb = out_fin + (size_t)b * NC;
#pragma unroll
    for (int m = 0; m < 2; m++) {
        const int c0 = 16 * (2 * mh + m) + g;
        float s0 = 0.0f, s1 = 0.0f;
#pragma unroll
        for (int nf = 0; nf < 4; nf++) {
            int d0 = 8 * nf + 2 * jm;
            *(float2*)&om[c0 * DD + d0] =
                make_float2(acc[m][nf][0], acc[m][nf][1]);
            *(float2*)&om[(c0 + 8) * DD + d0] =
                make_float2(acc[m][nf][2], acc[m][nf][3]);
            s0 += acc[m][nf][0] + acc[m][nf][1];
            s1 += acc[m][nf][2] + acc[m][nf][3];
        }
        // sum across the quad (lanes sharing g): covers all 32 d
#pragma unroll
        for (int o = 1; o <= 2; o <<= 1) {
            s0 += __shfl_xor_sync(0xffffffffu, s0, o);
            s1 += __shfl_xor_sync(0xffffffffu, s1, o);
        }
        if (jm == 0) { fb[c0] = s0; fb[c0 + 8] = s1; }
    }
}

extern "C" void kernel_launch(void* const* d_in, const int* in_sizes, int n_in,
                              void* d_out, int out_size) {
    const float* X = (const float*)d_in[0];
    const float* Y = (const float*)d_in[1];
    const float* K = (const float*)d_in[2];
    float* om = (float*)d_out;
    float* fin = om + (size_t)NB * NC * DD;

    wfrag_kernel<<<32, 256>>>(K);
    cin_mma_kernel<<<NB / 4, 256>>>(X, Y, om, fin);
}